// round 4
// baseline (speedup 1.0000x reference)
#include <cuda_runtime.h>
#include <math.h>

#define LTOT (2*64*32*1024)
#define ROWS 65536

__device__ float g_h5[LTOT];
__device__ float g_s3[LTOT];
__device__ float g_s5[LTOT];
__device__ float g_x1[LTOT];
__device__ float g_x2[LTOT];
__device__ float g_s [LTOT];
__device__ float g_yT[(size_t)ROWS * 64];

__device__ float g_gre[32], g_gim[32], g_qre[32], g_qim[32];
__device__ float g_sum1[64], g_sq1[64], g_sum2[64], g_sq2[64];
__device__ float g_a1[64], g_b1[64], g_a2[64], g_b2[64];

__device__ __forceinline__ float gelu_f(float v) {
    return 0.5f * v * (1.0f + erff(v * 0.70710678118654752f));
}

// K0: g = ifft_T(fw), q = ifft_T(fb); zero BN stats
__global__ void k_prep(const float* __restrict__ fw, const float* __restrict__ fb) {
    int n = threadIdx.x;
    if (n < 32) {
        double gr = 0, gi = 0, qr = 0, qi = 0;
        for (int k = 0; k < 32; k++) {
            double ang = 6.283185307179586476925 * (double)((k * n) & 31) / 32.0;
            double cs = cos(ang), sn = sin(ang);
            gr += (double)fw[k] * cs; gi += (double)fw[k] * sn;
            qr += (double)fb[k] * cs; qi += (double)fb[k] * sn;
        }
        g_gre[n] = (float)(gr / 32.0); g_gim[n] = (float)(gi / 32.0);
        g_qre[n] = (float)(qr / 32.0); g_qim[n] = (float)(qi / 32.0);
    }
    if (n < 64) { g_sum1[n] = 0.f; g_sq1[n] = 0.f; g_sum2[n] = 0.f; g_sq2[n] = 0.f; }
}

// K1: down GEMM [65536,384]x[64,384]^T + bias + GELU -> h5 NCDHW
// block: 128 rows x 64 channels, 128 threads, 8x8 per thread
__global__ void __launch_bounds__(128) k_down(const float* __restrict__ x,
                                              const float* __restrict__ w,
                                              const float* __restrict__ bias) {
    __shared__ __align__(16) float As[32][132];  // [k][m]
    __shared__ __align__(16) float Bs[32][68];   // [k][c]
    int tid = threadIdx.x;
    int r0 = blockIdx.x * 128;
    int rg = tid & 15;   // row group (8 rows)
    int cg = tid >> 4;   // 0..7 channel group (8 ch)
    float acc[8][8];
    #pragma unroll
    for (int i = 0; i < 8; i++)
        #pragma unroll
        for (int j = 0; j < 8; j++) acc[i][j] = 0.f;

    for (int k0 = 0; k0 < 384; k0 += 32) {
        // As: 128x32, float4 loads (8 per thread)
        #pragma unroll
        for (int i = 0; i < 8; i++) {
            int idx4 = tid + i * 128;
            int k4 = (idx4 & 7) * 4, m = idx4 >> 3;
            float4 v = *reinterpret_cast<const float4*>(&x[(size_t)(r0 + m) * 384 + k0 + k4]);
            As[k4 + 0][m] = v.x; As[k4 + 1][m] = v.y; As[k4 + 2][m] = v.z; As[k4 + 3][m] = v.w;
        }
        // Bs: 64x32, float4 loads (4 per thread)
        #pragma unroll
        for (int i = 0; i < 4; i++) {
            int idx4 = tid + i * 128;
            int k4 = (idx4 & 7) * 4, c = idx4 >> 3;
            float4 v = *reinterpret_cast<const float4*>(&w[c * 384 + k0 + k4]);
            Bs[k4 + 0][c] = v.x; Bs[k4 + 1][c] = v.y; Bs[k4 + 2][c] = v.z; Bs[k4 + 3][c] = v.w;
        }
        __syncthreads();
        #pragma unroll
        for (int k = 0; k < 32; k++) {
            float4 a0 = *reinterpret_cast<const float4*>(&As[k][rg * 8]);
            float4 a1 = *reinterpret_cast<const float4*>(&As[k][rg * 8 + 4]);
            float4 b0 = *reinterpret_cast<const float4*>(&Bs[k][cg * 8]);
            float4 b1 = *reinterpret_cast<const float4*>(&Bs[k][cg * 8 + 4]);
            float av[8] = {a0.x, a0.y, a0.z, a0.w, a1.x, a1.y, a1.z, a1.w};
            float bv[8] = {b0.x, b0.y, b0.z, b0.w, b1.x, b1.y, b1.z, b1.w};
            #pragma unroll
            for (int i = 0; i < 8; i++)
                #pragma unroll
                for (int j = 0; j < 8; j++)
                    acc[i][j] = fmaf(av[i], bv[j], acc[i][j]);
        }
        __syncthreads();
    }
    int row0 = r0 + rg * 8;
    int bt = row0 >> 10, hw0 = row0 & 1023;
    int b = bt >> 5, t = bt & 31;
    #pragma unroll
    for (int j = 0; j < 8; j++) {
        int c = cg * 8 + j;
        float bsv = bias[c];
        float* dst = &g_h5[(size_t)((b * 64 + c) * 32 + t) * 1024 + hw0];
        float4 o0, o1;
        o0.x = gelu_f(acc[0][j] + bsv); o0.y = gelu_f(acc[1][j] + bsv);
        o0.z = gelu_f(acc[2][j] + bsv); o0.w = gelu_f(acc[3][j] + bsv);
        o1.x = gelu_f(acc[4][j] + bsv); o1.y = gelu_f(acc[5][j] + bsv);
        o1.z = gelu_f(acc[6][j] + bsv); o1.w = gelu_f(acc[7][j] + bsv);
        *reinterpret_cast<float4*>(dst) = o0;
        *reinterpret_cast<float4*>(dst + 4) = o1;
    }
}

// K2: spatial depthwise 3x3 and 5x5 per (b,c,t) slice
__global__ void __launch_bounds__(256) k_spatial(const float* __restrict__ w3g,
                                                 const float* __restrict__ b3g,
                                                 const float* __restrict__ w5g,
                                                 const float* __restrict__ b5g) {
    int bct = blockIdx.x;
    int c = (bct >> 5) & 63;
    __shared__ float tile[1024];
    __shared__ float w3[9], w5[25];
    int tid = threadIdx.x;
    if (tid < 9)  w3[tid] = w3g[c * 9 + tid];
    if (tid >= 32 && tid < 57) w5[tid - 32] = w5g[c * 25 + (tid - 32)];
    const float* src = g_h5 + (size_t)bct * 1024;
    for (int i = tid; i < 1024; i += 256) tile[i] = src[i];
    __syncthreads();
    float b3 = b3g[c], b5 = b5g[c];
    for (int p = tid; p < 1024; p += 256) {
        int h = p >> 5, wq = p & 31;
        float a3 = b3;
        #pragma unroll
        for (int dh = -1; dh <= 1; dh++) {
            int hh = h + dh;
            if ((unsigned)hh >= 32u) continue;
            #pragma unroll
            for (int dw = -1; dw <= 1; dw++) {
                int ww = wq + dw;
                if ((unsigned)ww >= 32u) continue;
                a3 = fmaf(tile[hh * 32 + ww], w3[(dh + 1) * 3 + dw + 1], a3);
            }
        }
        float a5 = b5;
        #pragma unroll
        for (int dh = -2; dh <= 2; dh++) {
            int hh = h + dh;
            if ((unsigned)hh >= 32u) continue;
            #pragma unroll
            for (int dw = -2; dw <= 2; dw++) {
                int ww = wq + dw;
                if ((unsigned)ww >= 32u) continue;
                a5 = fmaf(tile[hh * 32 + ww], w5[(dh + 2) * 5 + dw + 2], a5);
            }
        }
        g_s3[(size_t)bct * 1024 + p] = a3;
        g_s5[(size_t)bct * 1024 + p] = a5;
    }
}

// K3: temporal depthwise 3/5-tap + BN stats. Block = (bc, 128-hw chunk), smem tiled.
__global__ void __launch_bounds__(256) k_temporal(const float* __restrict__ w3g,
                                                  const float* __restrict__ b3g,
                                                  const float* __restrict__ w5g,
                                                  const float* __restrict__ b5g) {
    int bc  = blockIdx.x >> 3;          // 0..127
    int hw0 = (blockIdx.x & 7) << 7;    // 128-hw chunk
    int c = bc & 63;
    size_t base = (size_t)bc * 32768;
    __shared__ float s3t[32][128];
    __shared__ float s5t[32][128];
    int tid = threadIdx.x;
    for (int i = tid; i < 4096; i += 256) {
        int t = i >> 7, p = i & 127;
        s3t[t][p] = g_s3[base + (size_t)t * 1024 + hw0 + p];
        s5t[t][p] = g_s5[base + (size_t)t * 1024 + hw0 + p];
    }
    __syncthreads();
    float w3[3], w5[5];
    #pragma unroll
    for (int i = 0; i < 3; i++) w3[i] = w3g[c * 3 + i];
    #pragma unroll
    for (int i = 0; i < 5; i++) w5[i] = w5g[c * 5 + i];
    float b3 = b3g[c], b5 = b5g[c];
    float s1 = 0, q1 = 0, s2 = 0, q2 = 0;
    for (int i = tid; i < 4096; i += 256) {
        int t = i >> 7, p = i & 127;
        float a = b3;
        #pragma unroll
        for (int dt = -1; dt <= 1; dt++) {
            int tt = t + dt;
            if ((unsigned)tt < 32u) a = fmaf(s3t[tt][p], w3[dt + 1], a);
        }
        float e = b5;
        #pragma unroll
        for (int dt = -2; dt <= 2; dt++) {
            int tt = t + dt;
            if ((unsigned)tt < 32u) e = fmaf(s5t[tt][p], w5[dt + 2], e);
        }
        g_x1[base + (size_t)t * 1024 + hw0 + p] = a;
        g_x2[base + (size_t)t * 1024 + hw0 + p] = e;
        s1 += a; q1 = fmaf(a, a, q1);
        s2 += e; q2 = fmaf(e, e, q2);
    }
    #pragma unroll
    for (int off = 16; off; off >>= 1) {
        s1 += __shfl_down_sync(0xffffffffu, s1, off);
        q1 += __shfl_down_sync(0xffffffffu, q1, off);
        s2 += __shfl_down_sync(0xffffffffu, s2, off);
        q2 += __shfl_down_sync(0xffffffffu, q2, off);
    }
    __shared__ float red[4][8];
    int wid = threadIdx.x >> 5, lane = threadIdx.x & 31;
    if (lane == 0) { red[0][wid] = s1; red[1][wid] = q1; red[2][wid] = s2; red[3][wid] = q2; }
    __syncthreads();
    if (threadIdx.x == 0) {
        float a = 0, b = 0, c2 = 0, d = 0;
        for (int i = 0; i < 8; i++) { a += red[0][i]; b += red[1][i]; c2 += red[2][i]; d += red[3][i]; }
        atomicAdd(&g_sum1[c], a);  atomicAdd(&g_sq1[c], b);
        atomicAdd(&g_sum2[c], c2); atomicAdd(&g_sq2[c], d);
    }
}

// K4: BN scale/shift from stats
__global__ void k_bn(const float* __restrict__ g3, const float* __restrict__ b3,
                     const float* __restrict__ g5, const float* __restrict__ b5) {
    int c = threadIdx.x;
    const float inv = 1.0f / 65536.0f;
    float m1 = g_sum1[c] * inv;
    float v1 = g_sq1[c] * inv - m1 * m1;
    float a1 = g3[c] * rsqrtf(v1 + 1e-5f);
    g_a1[c] = a1; g_b1[c] = b3[c] - m1 * a1;
    float m2 = g_sum2[c] * inv;
    float v2 = g_sq2[c] * inv - m2 * m2;
    float a2 = g5[c] * rsqrtf(v2 + 1e-5f);
    g_a2[c] = a2; g_b2[c] = b5[c] - m2 * a2;
}

// K5: circulant T-conv (FFT branch) + BN-ReLU combine -> s
__global__ void __launch_bounds__(256) k_branch3() {
    int bc  = blockIdx.x >> 2;
    int hw0 = (blockIdx.x & 3) << 8;
    int c = bc & 63;
    size_t base = (size_t)bc * 32768;
    __shared__ float2 gg[64];
    __shared__ float2 qq[32];
    __shared__ __align__(16) float4 Vs[32][64];
    int tid = threadIdx.x;
    if (tid < 64) gg[tid] = make_float2(g_gre[tid & 31], g_gim[tid & 31]);
    if (tid < 32) qq[tid] = make_float2(g_qre[tid], g_qim[tid]);
    for (int i = tid; i < 2048; i += 256) {
        int t = i >> 6, q4 = i & 63;
        Vs[t][q4] = *reinterpret_cast<const float4*>(&g_h5[base + (size_t)t * 1024 + hw0 + q4 * 4]);
    }
    __syncthreads();
    int ty = tid >> 6;
    int tx = tid & 63;
    float re[8][4], im[8][4];
    #pragma unroll
    for (int i = 0; i < 8; i++)
        #pragma unroll
        for (int j = 0; j < 4; j++) { re[i][j] = 0.f; im[i][j] = 0.f; }
    for (int tau = 0; tau < 32; tau++) {
        float4 v = Vs[tau][tx];
        float vv[4] = {v.x, v.y, v.z, v.w};
        #pragma unroll
        for (int i = 0; i < 8; i++) {
            float2 g2 = gg[(ty * 8 + i - tau + 32) & 31];
            #pragma unroll
            for (int j = 0; j < 4; j++) {
                re[i][j] = fmaf(vv[j], g2.x, re[i][j]);
                im[i][j] = fmaf(vv[j], g2.y, im[i][j]);
            }
        }
    }
    float a1 = g_a1[c], b1 = g_b1[c], a2 = g_a2[c], b2v = g_b2[c];
    #pragma unroll
    for (int i = 0; i < 8; i++) {
        int t = ty * 8 + i;
        #pragma unroll
        for (int j = 0; j < 4; j++) {
            int hw = hw0 + tx * 4 + j;
            float rr = re[i][j], ii = im[i][j];
            if (hw == 0) { rr += qq[t].x; ii += qq[t].y; }
            float x3 = sqrtf(rr * rr + ii * ii);
            size_t idx = base + (size_t)t * 1024 + hw;
            float x1v = fmaxf(fmaf(g_x1[idx], a1, b1), 0.f);
            float x2v = fmaxf(fmaf(g_x2[idx], a2, b2v), 0.f);
            g_s[idx] = x1v + x2v + x3;
        }
    }
}

// K6: 64x64 channel mix + shortcut -> yT [row][c]
__global__ void __launch_bounds__(256) k_mix(const float* __restrict__ w2,
                                             const float* __restrict__ cb) {
    int bt  = blockIdx.x >> 3;
    int hw0 = (blockIdx.x & 7) << 7;
    int b = bt >> 5, t = bt & 31;
    __shared__ float W2t[64][64];
    __shared__ float st[64][128];
    int tid = threadIdx.x;
    for (int i = tid; i < 4096; i += 256) {
        int o = i & 63, cx = i >> 6;
        W2t[cx][o] = w2[o * 64 + cx];
    }
    for (int i = tid; i < 8192; i += 256) {
        int cx = i >> 7, p = i & 127;
        st[cx][p] = g_s[(size_t)((b * 64 + cx) * 32 + t) * 1024 + hw0 + p];
    }
    __syncthreads();
    int to  = tid & 15;
    int thw = tid >> 4;
    float acc[8][4];
    #pragma unroll
    for (int i = 0; i < 8; i++)
        #pragma unroll
        for (int j = 0; j < 4; j++) acc[i][j] = 0.f;
    for (int cx = 0; cx < 64; cx++) {
        float sv[8], wv[4];
        #pragma unroll
        for (int i = 0; i < 8; i++) sv[i] = st[cx][thw * 8 + i];
        #pragma unroll
        for (int j = 0; j < 4; j++) wv[j] = W2t[cx][to * 4 + j];
        #pragma unroll
        for (int i = 0; i < 8; i++)
            #pragma unroll
            for (int j = 0; j < 4; j++)
                acc[i][j] = fmaf(wv[j], sv[i], acc[i][j]);
    }
    float cbv[4];
    #pragma unroll
    for (int j = 0; j < 4; j++) cbv[j] = cb[to * 4 + j];
    #pragma unroll
    for (int i = 0; i < 8; i++) {
        int hw = hw0 + thw * 8 + i;
        float4 o4;
        o4.x = g_h5[(size_t)((b * 64 + to * 4 + 0) * 32 + t) * 1024 + hw] + acc[i][0] + cbv[0];
        o4.y = g_h5[(size_t)((b * 64 + to * 4 + 1) * 32 + t) * 1024 + hw] + acc[i][1] + cbv[1];
        o4.z = g_h5[(size_t)((b * 64 + to * 4 + 2) * 32 + t) * 1024 + hw] + acc[i][2] + cbv[2];
        o4.w = g_h5[(size_t)((b * 64 + to * 4 + 3) * 32 + t) * 1024 + hw] + acc[i][3] + cbv[3];
        *reinterpret_cast<float4*>(&g_yT[((size_t)bt * 1024 + hw) * 64 + to * 4]) = o4;
    }
}

// K7: up GEMM [65536,64]x[384,64]^T + bias + GELU + residual
// block: 128 rows x 128 cols, 256 threads, 8x8 per thread
__global__ void __launch_bounds__(256) k_up(const float* __restrict__ x,
                                            const float* __restrict__ w,
                                            const float* __restrict__ bias,
                                            float* __restrict__ out) {
    __shared__ __align__(16) float As[32][132];  // [k][m]
    __shared__ __align__(16) float Bs[32][132];  // [k][n]
    int tid = threadIdx.x;
    int r0 = blockIdx.x * 128;
    int n0 = blockIdx.y * 128;
    int rg = tid >> 4;   // 0..15 rows of 8
    int cg = tid & 15;   // 0..15 cols of 8
    float acc[8][8];
    #pragma unroll
    for (int i = 0; i < 8; i++)
        #pragma unroll
        for (int j = 0; j < 8; j++) acc[i][j] = 0.f;

    for (int k0 = 0; k0 < 64; k0 += 32) {
        #pragma unroll
        for (int i = 0; i < 4; i++) {
            int idx4 = tid + i * 256;
            int k4 = (idx4 & 7) * 4, m = idx4 >> 3;
            float4 v = *reinterpret_cast<const float4*>(&g_yT[(size_t)(r0 + m) * 64 + k0 + k4]);
            As[k4 + 0][m] = v.x; As[k4 + 1][m] = v.y; As[k4 + 2][m] = v.z; As[k4 + 3][m] = v.w;
        }
        #pragma unroll
        for (int i = 0; i < 4; i++) {
            int idx4 = tid + i * 256;
            int k4 = (idx4 & 7) * 4, n = idx4 >> 3;
            float4 v = *reinterpret_cast<const float4*>(&w[(size_t)(n0 + n) * 64 + k0 + k4]);
            Bs[k4 + 0][n] = v.x; Bs[k4 + 1][n] = v.y; Bs[k4 + 2][n] = v.z; Bs[k4 + 3][n] = v.w;
        }
        __syncthreads();
        #pragma unroll
        for (int k = 0; k < 32; k++) {
            float4 a0 = *reinterpret_cast<const float4*>(&As[k][rg * 8]);
            float4 a1 = *reinterpret_cast<const float4*>(&As[k][rg * 8 + 4]);
            float4 b0 = *reinterpret_cast<const float4*>(&Bs[k][cg * 8]);
            float4 b1 = *reinterpret_cast<const float4*>(&Bs[k][cg * 8 + 4]);
            float av[8] = {a0.x, a0.y, a0.z, a0.w, a1.x, a1.y, a1.z, a1.w};
            float bv[8] = {b0.x, b0.y, b0.z, b0.w, b1.x, b1.y, b1.z, b1.w};
            #pragma unroll
            for (int i = 0; i < 8; i++)
                #pragma unroll
                for (int j = 0; j < 8; j++)
                    acc[i][j] = fmaf(av[i], bv[j], acc[i][j]);
        }
        __syncthreads();
    }
    float bv8[8];
    #pragma unroll
    for (int j = 0; j < 8; j++) bv8[j] = bias[n0 + cg * 8 + j];
    #pragma unroll
    for (int i = 0; i < 8; i++) {
        int row = r0 + rg * 8 + i;
        const float* xin = &x[(size_t)row * 384 + n0 + cg * 8];
        float* op = &out[(size_t)row * 384 + n0 + cg * 8];
        float4 x0 = *reinterpret_cast<const float4*>(xin);
        float4 x1 = *reinterpret_cast<const float4*>(xin + 4);
        float4 o0, o1;
        o0.x = x0.x + gelu_f(acc[i][0] + bv8[0]);
        o0.y = x0.y + gelu_f(acc[i][1] + bv8[1]);
        o0.z = x0.z + gelu_f(acc[i][2] + bv8[2]);
        o0.w = x0.w + gelu_f(acc[i][3] + bv8[3]);
        o1.x = x1.x + gelu_f(acc[i][4] + bv8[4]);
        o1.y = x1.y + gelu_f(acc[i][5] + bv8[5]);
        o1.z = x1.z + gelu_f(acc[i][6] + bv8[6]);
        o1.w = x1.w + gelu_f(acc[i][7] + bv8[7]);
        *reinterpret_cast<float4*>(op) = o0;
        *reinterpret_cast<float4*>(op + 4) = o1;
    }
}

extern "C" void kernel_launch(void* const* d_in, const int* in_sizes, int n_in,
                              void* d_out, int out_size) {
    const float* x      = (const float*)d_in[0];
    const float* down_w = (const float*)d_in[1];
    const float* down_b = (const float*)d_in[2];
    const float* k31w   = (const float*)d_in[3];
    const float* k31b   = (const float*)d_in[4];
    const float* k32w   = (const float*)d_in[5];
    const float* k32b   = (const float*)d_in[6];
    const float* bn3g   = (const float*)d_in[7];
    const float* bn3b   = (const float*)d_in[8];
    const float* k51w   = (const float*)d_in[9];
    const float* k51b   = (const float*)d_in[10];
    const float* k52w   = (const float*)d_in[11];
    const float* k52b   = (const float*)d_in[12];
    const float* bn5g   = (const float*)d_in[13];
    const float* bn5b   = (const float*)d_in[14];
    const float* convw  = (const float*)d_in[15];
    const float* convb  = (const float*)d_in[16];
    const float* fw     = (const float*)d_in[17];
    const float* fb     = (const float*)d_in[18];
    const float* upw    = (const float*)d_in[19];
    const float* upb    = (const float*)d_in[20];
    float* out = (float*)d_out;

    k_prep    <<<1, 64>>>(fw, fb);
    k_down    <<<512, 128>>>(x, down_w, down_b);
    k_spatial <<<4096, 256>>>(k31w, k31b, k51w, k51b);
    k_temporal<<<1024, 256>>>(k32w, k32b, k52w, k52b);
    k_bn      <<<1, 64>>>(bn3g, bn3b, bn5g, bn5b);
    k_branch3 <<<512, 256>>>();
    k_mix     <<<512, 256>>>(convw, convb);
    {
        dim3 grid(ROWS / 128, 384 / 128);
        k_up <<<grid, 256>>>(x, upw, upb, out);
    }
}

// round 5
// speedup vs baseline: 1.2218x; 1.2218x over previous
#include <cuda_runtime.h>
#include <math.h>
#include <stdint.h>

#define LTOT (2*64*32*1024)
#define ROWS 65536

__device__ float g_h5[LTOT];
__device__ float g_s3[LTOT];
__device__ float g_s5[LTOT];
__device__ float g_x1[LTOT];
__device__ float g_x2[LTOT];
__device__ float g_s [LTOT];
__device__ float g_yT[(size_t)ROWS * 64];

__device__ float g_gre[32], g_gim[32], g_qre[32], g_qim[32];
__device__ float g_sum1[64], g_sq1[64], g_sum2[64], g_sq2[64];
__device__ float g_a1[64], g_b1[64], g_a2[64], g_b2[64];

__device__ __forceinline__ float gelu_f(float v) {
    return 0.5f * v * (1.0f + erff(v * 0.70710678118654752f));
}

__device__ __forceinline__ uint32_t f2tf32(float f) {
    uint32_t r;
    asm("cvt.rna.tf32.f32 %0, %1;" : "=r"(r) : "f"(f));
    return r;
}

__device__ __forceinline__ void mma_tf32(float c[4], uint32_t a0, uint32_t a1,
                                         uint32_t a2, uint32_t a3,
                                         uint32_t b0, uint32_t b1) {
    asm volatile(
        "mma.sync.aligned.m16n8k8.row.col.f32.tf32.tf32.f32 "
        "{%0,%1,%2,%3}, {%4,%5,%6,%7}, {%8,%9}, {%0,%1,%2,%3};"
        : "+f"(c[0]), "+f"(c[1]), "+f"(c[2]), "+f"(c[3])
        : "r"(a0), "r"(a1), "r"(a2), "r"(a3), "r"(b0), "r"(b1));
}

// K0: g = ifft_T(fw), q = ifft_T(fb); zero BN stats
__global__ void k_prep(const float* __restrict__ fw, const float* __restrict__ fb) {
    int n = threadIdx.x;
    if (n < 32) {
        double gr = 0, gi = 0, qr = 0, qi = 0;
        for (int k = 0; k < 32; k++) {
            double ang = 6.283185307179586476925 * (double)((k * n) & 31) / 32.0;
            double cs = cos(ang), sn = sin(ang);
            gr += (double)fw[k] * cs; gi += (double)fw[k] * sn;
            qr += (double)fb[k] * cs; qi += (double)fb[k] * sn;
        }
        g_gre[n] = (float)(gr / 32.0); g_gim[n] = (float)(gi / 32.0);
        g_qre[n] = (float)(qr / 32.0); g_qim[n] = (float)(qi / 32.0);
    }
    if (n < 64) { g_sum1[n] = 0.f; g_sq1[n] = 0.f; g_sum2[n] = 0.f; g_sq2[n] = 0.f; }
}

// K1: down GEMM (tf32 tensor cores) [65536,384]x[64,384]^T + bias + GELU -> h5 NCDHW
// block 128M x 64N, 256 threads = 8 warps (4M x 2N), warp tile 32x32
__global__ void __launch_bounds__(256) k_down(const float* __restrict__ x,
                                              const float* __restrict__ w,
                                              const float* __restrict__ bias) {
    __shared__ uint32_t As[128][36];
    __shared__ uint32_t Bs[64][36];
    int tid = threadIdx.x;
    int r0 = blockIdx.x * 128;
    int wid = tid >> 5, lane = tid & 31;
    int g = lane >> 2, tig = lane & 3;
    int warp_m = (wid & 3) * 32;
    int warp_n = (wid >> 2) * 32;

    float acc[2][4][4];
    #pragma unroll
    for (int i = 0; i < 2; i++)
        #pragma unroll
        for (int j = 0; j < 4; j++)
            #pragma unroll
            for (int l = 0; l < 4; l++) acc[i][j][l] = 0.f;

    for (int k0 = 0; k0 < 384; k0 += 32) {
        #pragma unroll
        for (int i = 0; i < 4; i++) {
            int idx4 = tid + i * 256;
            int m = idx4 >> 3, k4 = (idx4 & 7) * 4;
            float4 v = *reinterpret_cast<const float4*>(&x[(size_t)(r0 + m) * 384 + k0 + k4]);
            As[m][k4 + 0] = f2tf32(v.x); As[m][k4 + 1] = f2tf32(v.y);
            As[m][k4 + 2] = f2tf32(v.z); As[m][k4 + 3] = f2tf32(v.w);
        }
        #pragma unroll
        for (int i = 0; i < 2; i++) {
            int idx4 = tid + i * 256;
            int n = idx4 >> 3, k4 = (idx4 & 7) * 4;
            float4 v = *reinterpret_cast<const float4*>(&w[n * 384 + k0 + k4]);
            Bs[n][k4 + 0] = f2tf32(v.x); Bs[n][k4 + 1] = f2tf32(v.y);
            Bs[n][k4 + 2] = f2tf32(v.z); Bs[n][k4 + 3] = f2tf32(v.w);
        }
        __syncthreads();
        #pragma unroll
        for (int ks = 0; ks < 4; ks++) {
            int kk = ks * 8;
            uint32_t a[2][4];
            #pragma unroll
            for (int mf = 0; mf < 2; mf++) {
                int row = warp_m + mf * 16;
                a[mf][0] = As[row + g    ][kk + tig];
                a[mf][1] = As[row + g + 8][kk + tig];
                a[mf][2] = As[row + g    ][kk + tig + 4];
                a[mf][3] = As[row + g + 8][kk + tig + 4];
            }
            uint32_t b[4][2];
            #pragma unroll
            for (int nf = 0; nf < 4; nf++) {
                int col = warp_n + nf * 8;
                b[nf][0] = Bs[col + g][kk + tig];
                b[nf][1] = Bs[col + g][kk + tig + 4];
            }
            #pragma unroll
            for (int mf = 0; mf < 2; mf++)
                #pragma unroll
                for (int nf = 0; nf < 4; nf++)
                    mma_tf32(acc[mf][nf], a[mf][0], a[mf][1], a[mf][2], a[mf][3],
                             b[nf][0], b[nf][1]);
        }
        __syncthreads();
    }
    // epilogue: rows r0..r0+127 share bt (128 | 1024)
    int bt = r0 >> 10, hwbase = r0 & 1023;
    int b5i = bt >> 5, t = bt & 31;
    size_t planebase = (size_t)(b5i * 64) * 32768 + (size_t)t * 1024;
    #pragma unroll
    for (int nf = 0; nf < 4; nf++) {
        int c0 = warp_n + nf * 8 + 2 * tig;
        float bs0 = bias[c0], bs1 = bias[c0 + 1];
        #pragma unroll
        for (int mf = 0; mf < 2; mf++) {
            int m = warp_m + mf * 16 + g;
            size_t p0 = planebase + (size_t)c0 * 32768;
            g_h5[p0 + hwbase + m]                 = gelu_f(acc[mf][nf][0] + bs0);
            g_h5[p0 + 32768 + hwbase + m]         = gelu_f(acc[mf][nf][1] + bs1);
            g_h5[p0 + hwbase + m + 8]             = gelu_f(acc[mf][nf][2] + bs0);
            g_h5[p0 + 32768 + hwbase + m + 8]     = gelu_f(acc[mf][nf][3] + bs1);
        }
    }
}

// K2: spatial depthwise 3x3 and 5x5 per (b,c,t) slice
__global__ void __launch_bounds__(256) k_spatial(const float* __restrict__ w3g,
                                                 const float* __restrict__ b3g,
                                                 const float* __restrict__ w5g,
                                                 const float* __restrict__ b5g) {
    int bct = blockIdx.x;
    int c = (bct >> 5) & 63;
    __shared__ float tile[1024];
    __shared__ float w3[9], w5[25];
    int tid = threadIdx.x;
    if (tid < 9)  w3[tid] = w3g[c * 9 + tid];
    if (tid >= 32 && tid < 57) w5[tid - 32] = w5g[c * 25 + (tid - 32)];
    const float* src = g_h5 + (size_t)bct * 1024;
    for (int i = tid; i < 1024; i += 256) tile[i] = src[i];
    __syncthreads();
    float b3 = b3g[c], b5 = b5g[c];
    for (int p = tid; p < 1024; p += 256) {
        int h = p >> 5, wq = p & 31;
        float a3 = b3;
        #pragma unroll
        for (int dh = -1; dh <= 1; dh++) {
            int hh = h + dh;
            if ((unsigned)hh >= 32u) continue;
            #pragma unroll
            for (int dw = -1; dw <= 1; dw++) {
                int ww = wq + dw;
                if ((unsigned)ww >= 32u) continue;
                a3 = fmaf(tile[hh * 32 + ww], w3[(dh + 1) * 3 + dw + 1], a3);
            }
        }
        float a5 = b5;
        #pragma unroll
        for (int dh = -2; dh <= 2; dh++) {
            int hh = h + dh;
            if ((unsigned)hh >= 32u) continue;
            #pragma unroll
            for (int dw = -2; dw <= 2; dw++) {
                int ww = wq + dw;
                if ((unsigned)ww >= 32u) continue;
                a5 = fmaf(tile[hh * 32 + ww], w5[(dh + 2) * 5 + dw + 2], a5);
            }
        }
        g_s3[(size_t)bct * 1024 + p] = a3;
        g_s5[(size_t)bct * 1024 + p] = a5;
    }
}

// K3: temporal depthwise 3/5-tap + BN stats
__global__ void __launch_bounds__(256) k_temporal(const float* __restrict__ w3g,
                                                  const float* __restrict__ b3g,
                                                  const float* __restrict__ w5g,
                                                  const float* __restrict__ b5g) {
    int bc  = blockIdx.x >> 3;
    int hw0 = (blockIdx.x & 7) << 7;
    int c = bc & 63;
    size_t base = (size_t)bc * 32768;
    __shared__ float s3t[32][128];
    __shared__ float s5t[32][128];
    int tid = threadIdx.x;
    for (int i = tid; i < 4096; i += 256) {
        int t = i >> 7, p = i & 127;
        s3t[t][p] = g_s3[base + (size_t)t * 1024 + hw0 + p];
        s5t[t][p] = g_s5[base + (size_t)t * 1024 + hw0 + p];
    }
    __syncthreads();
    float w3[3], w5[5];
    #pragma unroll
    for (int i = 0; i < 3; i++) w3[i] = w3g[c * 3 + i];
    #pragma unroll
    for (int i = 0; i < 5; i++) w5[i] = w5g[c * 5 + i];
    float b3 = b3g[c], b5 = b5g[c];
    float s1 = 0, q1 = 0, s2 = 0, q2 = 0;
    for (int i = tid; i < 4096; i += 256) {
        int t = i >> 7, p = i & 127;
        float a = b3;
        #pragma unroll
        for (int dt = -1; dt <= 1; dt++) {
            int tt = t + dt;
            if ((unsigned)tt < 32u) a = fmaf(s3t[tt][p], w3[dt + 1], a);
        }
        float e = b5;
        #pragma unroll
        for (int dt = -2; dt <= 2; dt++) {
            int tt = t + dt;
            if ((unsigned)tt < 32u) e = fmaf(s5t[tt][p], w5[dt + 2], e);
        }
        g_x1[base + (size_t)t * 1024 + hw0 + p] = a;
        g_x2[base + (size_t)t * 1024 + hw0 + p] = e;
        s1 += a; q1 = fmaf(a, a, q1);
        s2 += e; q2 = fmaf(e, e, q2);
    }
    #pragma unroll
    for (int off = 16; off; off >>= 1) {
        s1 += __shfl_down_sync(0xffffffffu, s1, off);
        q1 += __shfl_down_sync(0xffffffffu, q1, off);
        s2 += __shfl_down_sync(0xffffffffu, s2, off);
        q2 += __shfl_down_sync(0xffffffffu, q2, off);
    }
    __shared__ float red[4][8];
    int wid = threadIdx.x >> 5, lane = threadIdx.x & 31;
    if (lane == 0) { red[0][wid] = s1; red[1][wid] = q1; red[2][wid] = s2; red[3][wid] = q2; }
    __syncthreads();
    if (threadIdx.x == 0) {
        float a = 0, b = 0, c2 = 0, d = 0;
        for (int i = 0; i < 8; i++) { a += red[0][i]; b += red[1][i]; c2 += red[2][i]; d += red[3][i]; }
        atomicAdd(&g_sum1[c], a);  atomicAdd(&g_sq1[c], b);
        atomicAdd(&g_sum2[c], c2); atomicAdd(&g_sq2[c], d);
    }
}

// K4: BN scale/shift
__global__ void k_bn(const float* __restrict__ g3, const float* __restrict__ b3,
                     const float* __restrict__ g5, const float* __restrict__ b5) {
    int c = threadIdx.x;
    const float inv = 1.0f / 65536.0f;
    float m1 = g_sum1[c] * inv;
    float v1 = g_sq1[c] * inv - m1 * m1;
    float a1 = g3[c] * rsqrtf(v1 + 1e-5f);
    g_a1[c] = a1; g_b1[c] = b3[c] - m1 * a1;
    float m2 = g_sum2[c] * inv;
    float v2 = g_sq2[c] * inv - m2 * m2;
    float a2 = g5[c] * rsqrtf(v2 + 1e-5f);
    g_a2[c] = a2; g_b2[c] = b5[c] - m2 * a2;
}

// K5: circulant T-conv (FFT branch) + BN-ReLU combine -> s
__global__ void __launch_bounds__(256) k_branch3() {
    int bc  = blockIdx.x >> 2;
    int hw0 = (blockIdx.x & 3) << 8;
    int c = bc & 63;
    size_t base = (size_t)bc * 32768;
    __shared__ float2 gg[64];
    __shared__ float2 qq[32];
    __shared__ __align__(16) float4 Vs[32][64];
    int tid = threadIdx.x;
    if (tid < 64) gg[tid] = make_float2(g_gre[tid & 31], g_gim[tid & 31]);
    if (tid < 32) qq[tid] = make_float2(g_qre[tid], g_qim[tid]);
    for (int i = tid; i < 2048; i += 256) {
        int t = i >> 6, q4 = i & 63;
        Vs[t][q4] = *reinterpret_cast<const float4*>(&g_h5[base + (size_t)t * 1024 + hw0 + q4 * 4]);
    }
    __syncthreads();
    int ty = tid >> 6;
    int tx = tid & 63;
    float re[8][4], im[8][4];
    #pragma unroll
    for (int i = 0; i < 8; i++)
        #pragma unroll
        for (int j = 0; j < 4; j++) { re[i][j] = 0.f; im[i][j] = 0.f; }
    for (int tau = 0; tau < 32; tau++) {
        float4 v = Vs[tau][tx];
        float vv[4] = {v.x, v.y, v.z, v.w};
        #pragma unroll
        for (int i = 0; i < 8; i++) {
            float2 g2 = gg[(ty * 8 + i - tau + 32) & 31];
            #pragma unroll
            for (int j = 0; j < 4; j++) {
                re[i][j] = fmaf(vv[j], g2.x, re[i][j]);
                im[i][j] = fmaf(vv[j], g2.y, im[i][j]);
            }
        }
    }
    float a1 = g_a1[c], b1 = g_b1[c], a2 = g_a2[c], b2v = g_b2[c];
    #pragma unroll
    for (int i = 0; i < 8; i++) {
        int t = ty * 8 + i;
        #pragma unroll
        for (int j = 0; j < 4; j++) {
            int hw = hw0 + tx * 4 + j;
            float rr = re[i][j], ii = im[i][j];
            if (hw == 0) { rr += qq[t].x; ii += qq[t].y; }
            float x3 = sqrtf(rr * rr + ii * ii);
            size_t idx = base + (size_t)t * 1024 + hw;
            float x1v = fmaxf(fmaf(g_x1[idx], a1, b1), 0.f);
            float x2v = fmaxf(fmaf(g_x2[idx], a2, b2v), 0.f);
            g_s[idx] = x1v + x2v + x3;
        }
    }
}

// K6: 64x64 channel mix + shortcut -> yT [row][c]
__global__ void __launch_bounds__(256) k_mix(const float* __restrict__ w2,
                                             const float* __restrict__ cb) {
    int bt  = blockIdx.x >> 3;
    int hw0 = (blockIdx.x & 7) << 7;
    int b = bt >> 5, t = bt & 31;
    __shared__ float W2t[64][64];
    __shared__ float st[64][128];
    int tid = threadIdx.x;
    for (int i = tid; i < 4096; i += 256) {
        int o = i & 63, cx = i >> 6;
        W2t[cx][o] = w2[o * 64 + cx];
    }
    for (int i = tid; i < 8192; i += 256) {
        int cx = i >> 7, p = i & 127;
        st[cx][p] = g_s[(size_t)((b * 64 + cx) * 32 + t) * 1024 + hw0 + p];
    }
    __syncthreads();
    int to  = tid & 15;
    int thw = tid >> 4;
    float acc[8][4];
    #pragma unroll
    for (int i = 0; i < 8; i++)
        #pragma unroll
        for (int j = 0; j < 4; j++) acc[i][j] = 0.f;
    for (int cx = 0; cx < 64; cx++) {
        float sv[8], wv[4];
        #pragma unroll
        for (int i = 0; i < 8; i++) sv[i] = st[cx][thw * 8 + i];
        #pragma unroll
        for (int j = 0; j < 4; j++) wv[j] = W2t[cx][to * 4 + j];
        #pragma unroll
        for (int i = 0; i < 8; i++)
            #pragma unroll
            for (int j = 0; j < 4; j++)
                acc[i][j] = fmaf(wv[j], sv[i], acc[i][j]);
    }
    float cbv[4];
    #pragma unroll
    for (int j = 0; j < 4; j++) cbv[j] = cb[to * 4 + j];
    #pragma unroll
    for (int i = 0; i < 8; i++) {
        int hw = hw0 + thw * 8 + i;
        float4 o4;
        o4.x = g_h5[(size_t)((b * 64 + to * 4 + 0) * 32 + t) * 1024 + hw] + acc[i][0] + cbv[0];
        o4.y = g_h5[(size_t)((b * 64 + to * 4 + 1) * 32 + t) * 1024 + hw] + acc[i][1] + cbv[1];
        o4.z = g_h5[(size_t)((b * 64 + to * 4 + 2) * 32 + t) * 1024 + hw] + acc[i][2] + cbv[2];
        o4.w = g_h5[(size_t)((b * 64 + to * 4 + 3) * 32 + t) * 1024 + hw] + acc[i][3] + cbv[3];
        *reinterpret_cast<float4*>(&g_yT[((size_t)bt * 1024 + hw) * 64 + to * 4]) = o4;
    }
}

// K7: up GEMM (tf32 tensor cores) [65536,64]x[384,64]^T + bias + GELU + residual
// block 128M x 128N, 256 threads = 8 warps (2M x 4N), warp tile 64x32
__global__ void __launch_bounds__(256) k_up(const float* __restrict__ x,
                                            const float* __restrict__ w,
                                            const float* __restrict__ bias,
                                            float* __restrict__ out) {
    __shared__ uint32_t As[128][36];
    __shared__ uint32_t Bs[128][36];
    int tid = threadIdx.x;
    int r0 = blockIdx.x * 128;
    int n0 = blockIdx.y * 128;
    int wid = tid >> 5, lane = tid & 31;
    int g = lane >> 2, tig = lane & 3;
    int warp_m = (wid & 1) * 64;
    int warp_n = (wid >> 1) * 32;

    float acc[4][4][4];
    #pragma unroll
    for (int i = 0; i < 4; i++)
        #pragma unroll
        for (int j = 0; j < 4; j++)
            #pragma unroll
            for (int l = 0; l < 4; l++) acc[i][j][l] = 0.f;

    for (int k0 = 0; k0 < 64; k0 += 32) {
        #pragma unroll
        for (int i = 0; i < 4; i++) {
            int idx4 = tid + i * 256;
            int m = idx4 >> 3, k4 = (idx4 & 7) * 4;
            float4 v = *reinterpret_cast<const float4*>(&g_yT[(size_t)(r0 + m) * 64 + k0 + k4]);
            As[m][k4 + 0] = f2tf32(v.x); As[m][k4 + 1] = f2tf32(v.y);
            As[m][k4 + 2] = f2tf32(v.z); As[m][k4 + 3] = f2tf32(v.w);
        }
        #pragma unroll
        for (int i = 0; i < 4; i++) {
            int idx4 = tid + i * 256;
            int n = idx4 >> 3, k4 = (idx4 & 7) * 4;
            float4 v = *reinterpret_cast<const float4*>(&w[(size_t)(n0 + n) * 64 + k0 + k4]);
            Bs[n][k4 + 0] = f2tf32(v.x); Bs[n][k4 + 1] = f2tf32(v.y);
            Bs[n][k4 + 2] = f2tf32(v.z); Bs[n][k4 + 3] = f2tf32(v.w);
        }
        __syncthreads();
        #pragma unroll
        for (int ks = 0; ks < 4; ks++) {
            int kk = ks * 8;
            uint32_t a[4][4];
            #pragma unroll
            for (int mf = 0; mf < 4; mf++) {
                int row = warp_m + mf * 16;
                a[mf][0] = As[row + g    ][kk + tig];
                a[mf][1] = As[row + g + 8][kk + tig];
                a[mf][2] = As[row + g    ][kk + tig + 4];
                a[mf][3] = As[row + g + 8][kk + tig + 4];
            }
            uint32_t b[4][2];
            #pragma unroll
            for (int nf = 0; nf < 4; nf++) {
                int col = warp_n + nf * 8;
                b[nf][0] = Bs[col + g][kk + tig];
                b[nf][1] = Bs[col + g][kk + tig + 4];
            }
            #pragma unroll
            for (int mf = 0; mf < 4; mf++)
                #pragma unroll
                for (int nf = 0; nf < 4; nf++)
                    mma_tf32(acc[mf][nf], a[mf][0], a[mf][1], a[mf][2], a[mf][3],
                             b[nf][0], b[nf][1]);
        }
        __syncthreads();
    }
    #pragma unroll
    for (int nf = 0; nf < 4; nf++) {
        int col = n0 + warp_n + nf * 8 + 2 * tig;
        float bs0 = bias[col], bs1 = bias[col + 1];
        #pragma unroll
        for (int mf = 0; mf < 4; mf++) {
            #pragma unroll
            for (int half = 0; half < 2; half++) {
                int row = r0 + warp_m + mf * 16 + g + half * 8;
                float c0 = acc[mf][nf][half * 2 + 0];
                float c1 = acc[mf][nf][half * 2 + 1];
                const float2 xin = *reinterpret_cast<const float2*>(&x[(size_t)row * 384 + col]);
                float2 o;
                o.x = xin.x + gelu_f(c0 + bs0);
                o.y = xin.y + gelu_f(c1 + bs1);
                *reinterpret_cast<float2*>(&out[(size_t)row * 384 + col]) = o;
            }
        }
    }
}

extern "C" void kernel_launch(void* const* d_in, const int* in_sizes, int n_in,
                              void* d_out, int out_size) {
    const float* x      = (const float*)d_in[0];
    const float* down_w = (const float*)d_in[1];
    const float* down_b = (const float*)d_in[2];
    const float* k31w   = (const float*)d_in[3];
    const float* k31b   = (const float*)d_in[4];
    const float* k32w   = (const float*)d_in[5];
    const float* k32b   = (const float*)d_in[6];
    const float* bn3g   = (const float*)d_in[7];
    const float* bn3b   = (const float*)d_in[8];
    const float* k51w   = (const float*)d_in[9];
    const float* k51b   = (const float*)d_in[10];
    const float* k52w   = (const float*)d_in[11];
    const float* k52b   = (const float*)d_in[12];
    const float* bn5g   = (const float*)d_in[13];
    const float* bn5b   = (const float*)d_in[14];
    const float* convw  = (const float*)d_in[15];
    const float* convb  = (const float*)d_in[16];
    const float* fw     = (const float*)d_in[17];
    const float* fb     = (const float*)d_in[18];
    const float* upw    = (const float*)d_in[19];
    const float* upb    = (const float*)d_in[20];
    float* out = (float*)d_out;

    k_prep    <<<1, 64>>>(fw, fb);
    k_down    <<<512, 256>>>(x, down_w, down_b);
    k_spatial <<<4096, 256>>>(k31w, k31b, k51w, k51b);
    k_temporal<<<1024, 256>>>(k32w, k32b, k52w, k52b);
    k_bn      <<<1, 64>>>(bn3g, bn3b, bn5g, bn5b);
    k_branch3 <<<512, 256>>>();
    k_mix     <<<512, 256>>>(convw, convb);
    {
        dim3 grid(ROWS / 128, 384 / 128);
        k_up <<<grid, 256>>>(x, upw, upb, out);
    }
}